// round 15
// baseline (speedup 1.0000x reference)
#include <cuda_runtime.h>
#include <cuda_fp16.h>
#include <cuda_bf16.h>

#define N_NODES 100000
#define E_MAX   640000
#define DIM     128
#define SCAN_CHUNK 1000         // counters per scan block
#define SCAN_NBLK  100          // 100 * 1000 = 100000

// Normalized feature cache, fp16: 25.6 MB.
__device__ uint4 g_hn[(size_t)N_NODES * DIM * 2 / 16];
// Exact-CSR scratch (total ~6.3 MB -- keeps h L2-resident, unlike round 14).
__device__ int  g_cnt[N_NODES];
__device__ int  g_off[N_NODES + 1];
__device__ int  g_cur[N_NODES];
__device__ int  g_bsum[SCAN_NBLK];
__device__ int2 g_pair[E_MAX];          // (dst, edge_id) in CSR order

// Kernel 1: TWO rows per warp, normalize -> fp16 cache. Also zeroes counters.
__global__ void normalize_fp16_kernel(const float* __restrict__ h, int n) {
    int tid = blockIdx.x * blockDim.x + threadIdx.x;
    if (tid < N_NODES) g_cnt[tid] = 0;

    int warp_id = tid >> 5;
    int lane = threadIdx.x & 31;
    int r0 = warp_id * 2;
    int r1 = r0 + 1;
    if (r0 >= n) return;
    bool has_r1 = (r1 < n);
    int r1c = has_r1 ? r1 : r0;

    const float4 v0 = __ldg(reinterpret_cast<const float4*>(h + (size_t)r0 * DIM) + lane);
    const float4 v1 = __ldg(reinterpret_cast<const float4*>(h + (size_t)r1c * DIM) + lane);

    float s0 = v0.x * v0.x + v0.y * v0.y + v0.z * v0.z + v0.w * v0.w;
    float s1 = v1.x * v1.x + v1.y * v1.y + v1.z * v1.z + v1.w * v1.w;
    #pragma unroll
    for (int off = 16; off > 0; off >>= 1) {
        s0 += __shfl_xor_sync(0xFFFFFFFFu, s0, off);
        s1 += __shfl_xor_sync(0xFFFFFFFFu, s1, off);
    }

    float inv0 = 1.0f / fmaxf(sqrtf(s0), 1e-12f);
    float inv1 = 1.0f / fmaxf(sqrtf(s1), 1e-12f);

    __half2 a0 = __floats2half2_rn(v0.x * inv0, v0.y * inv0);
    __half2 a1 = __floats2half2_rn(v0.z * inv0, v0.w * inv0);
    uint2 p0 = make_uint2(*reinterpret_cast<unsigned*>(&a0),
                          *reinterpret_cast<unsigned*>(&a1));
    reinterpret_cast<uint2*>(g_hn)[(size_t)r0 * 32 + lane] = p0;

    if (has_r1) {
        __half2 b0 = __floats2half2_rn(v1.x * inv1, v1.y * inv1);
        __half2 b1 = __floats2half2_rn(v1.z * inv1, v1.w * inv1);
        uint2 p1 = make_uint2(*reinterpret_cast<unsigned*>(&b0),
                              *reinterpret_cast<unsigned*>(&b1));
        reinterpret_cast<uint2*>(g_hn)[(size_t)r1 * 32 + lane] = p1;
    }
}

// Kernel 2: per-node degree count. Atomics spread over 100k addresses
// (~6.4-deep chains -- the round-9 failure was 205-deep on 3125 addresses).
__global__ void count_kernel(const int* __restrict__ src, int e, int n) {
    int i = blockIdx.x * blockDim.x + threadIdx.x;
    if (i >= e) return;
    int s = min(max(__ldg(src + i), 0), min(n, N_NODES) - 1);
    atomicAdd(&g_cnt[s], 1);
}

// Kernel 3a: block-local exclusive scan. 100 blocks x 1000 counters each.
__global__ void scan_local_kernel() {
    __shared__ int ssum[1024];
    int t = threadIdx.x;
    int base = blockIdx.x * SCAN_CHUNK;
    int c = (t < SCAN_CHUNK) ? g_cnt[base + t] : 0;
    ssum[t] = c;
    __syncthreads();
    for (int off = 1; off < 1024; off <<= 1) {
        int v = ssum[t];
        int add = (t >= off) ? ssum[t - off] : 0;
        __syncthreads();
        ssum[t] = v + add;
        __syncthreads();
    }
    if (t < SCAN_CHUNK) g_off[base + t] = ssum[t] - c;   // local exclusive
    if (t == SCAN_CHUNK - 1) g_bsum[blockIdx.x] = ssum[t];  // block total
}

// Kernel 3b: add block prefix; produce final offsets + scatter cursors.
__global__ void scan_fixup_kernel() {
    __shared__ int sb[128];
    int t = threadIdx.x;
    int b = blockIdx.x;
    sb[t] = (t < SCAN_NBLK && t < b) ? g_bsum[t] : 0;
    __syncthreads();
    for (int off = 64; off > 0; off >>= 1) {
        if (t < off) sb[t] += sb[t + off];
        __syncthreads();
    }
    int prefix = sb[0];
    __syncthreads();

    int base = b * SCAN_CHUNK;
    for (int j = t; j < SCAN_CHUNK; j += blockDim.x) {
        int v = g_off[base + j] + prefix;
        g_off[base + j] = v;
        g_cur[base + j] = v;
    }
    if (b == SCAN_NBLK - 1 && t == 0)
        g_off[N_NODES] = prefix + g_bsum[SCAN_NBLK - 1];
}

// Kernel 4: scatter (dst, edge_id) into CSR order. Slot order within a node
// is nondeterministic, but per-edge outputs are order-invariant.
__global__ void scatter_kernel(const int* __restrict__ src,
                               const int* __restrict__ dst, int e, int n) {
    int i = blockIdx.x * blockDim.x + threadIdx.x;
    if (i >= e) return;
    int nn = min(n, N_NODES);
    int s = min(max(__ldg(src + i), 0), nn - 1);
    int d = min(max(__ldg(dst + i), 0), nn - 1);
    int pos = atomicAdd(&g_cur[s], 1);
    if (pos < E_MAX)
        g_pair[pos] = make_int2(d, i);
}

// Dot of 8 fp16 pairs in two uint4's, fp32 accumulation.
__device__ __forceinline__ float dot8h(uint4 a, uint4 b) {
    float acc = 0.0f;
    #pragma unroll
    for (int w = 0; w < 4; w++) {
        unsigned ua = (&a.x)[w], ub = (&b.x)[w];
        __half2 ha = *reinterpret_cast<__half2*>(&ua);
        __half2 hb = *reinterpret_cast<__half2*>(&ub);
        float2 fa = __half22float2(ha);
        float2 fb = __half22float2(hb);
        acc = fmaf(fa.x, fb.x, acc);
        acc = fmaf(fa.y, fb.y, acc);
    }
    return acc;
}

// Kernel 5: one warp per node. Src row loaded ONCE (4 groups issue identical
// addresses -> warp coalescer dedups). 8 edges per iteration in two
// front-batched quad chains (round-12 ILP shape), 8 lanes per edge.
__global__ void __launch_bounds__(256)
sddmm_csr_kernel(float* __restrict__ out, int n) {
    int warp_id = (blockIdx.x * blockDim.x + threadIdx.x) >> 5;
    int lane = threadIdx.x & 31;
    if (warp_id >= n || warp_id >= N_NODES) return;
    int node = warp_id;

    int off0 = __ldg(g_off + node);
    int cnt  = __ldg(g_off + node + 1) - off0;
    if (cnt <= 0) return;

    int l = lane & 7;             // lane within 8-lane group
    int g = lane >> 3;            // group 0..3

    const uint4* row = g_hn + (size_t)node * 16;
    uint4 a_lo = __ldg(row + l);      // dedup'd across groups
    uint4 a_hi = __ldg(row + 8 + l);

    const int2* pairs = g_pair + off0;

    for (int k0 = 0; k0 < cnt; k0 += 8) {
        int ka = k0 + g;
        int kb = k0 + 4 + g;
        bool va = (ka < cnt);
        bool vb = (kb < cnt);

        int2 pa = __ldg(pairs + (va ? ka : 0));
        int2 pb = __ldg(pairs + (vb ? kb : 0));

        const uint4* ra = g_hn + (size_t)pa.x * 16;
        const uint4* rb = g_hn + (size_t)pb.x * 16;

        uint4 b0lo = __ldg(ra + l);
        uint4 b0hi = __ldg(ra + 8 + l);
        uint4 b1lo = __ldg(rb + l);
        uint4 b1hi = __ldg(rb + 8 + l);

        float acc0 = dot8h(a_lo, b0lo) + dot8h(a_hi, b0hi);
        float acc1 = dot8h(a_lo, b1lo) + dot8h(a_hi, b1hi);

        #pragma unroll
        for (int off = 4; off > 0; off >>= 1) {
            acc0 += __shfl_xor_sync(0xFFFFFFFFu, acc0, off);
            acc1 += __shfl_xor_sync(0xFFFFFFFFu, acc1, off);
        }

        if (l == 0) {
            if (va) out[pa.y] = acc0;
            if (vb) out[pb.y] = acc1;
        }
    }
}

extern "C" void kernel_launch(void* const* d_in, const int* in_sizes, int n_in,
                              void* d_out, int out_size) {
    const float* h   = (const float*)d_in[0];
    const int*   src = (const int*)d_in[1];   // int32 (JAX demotes int64)
    const int*   dst = (const int*)d_in[2];
    float* out = (float*)d_out;

    int n = in_sizes[0] / DIM;     // 100000
    int e = in_sizes[1];           // 640000

    {   // K1: normalize + zero counters
        int warps = (n + 1) / 2;
        int blocks = (warps + 7) / 8;
        normalize_fp16_kernel<<<blocks, 256>>>(h, n);
    }
    {   // K2: degree histogram
        int blocks = (e + 255) / 256;
        count_kernel<<<blocks, 256>>>(src, e, n);
    }
    scan_local_kernel<<<SCAN_NBLK, 1024>>>();
    scan_fixup_kernel<<<SCAN_NBLK, 128>>>();
    {   // K4: scatter into CSR
        int blocks = (e + 255) / 256;
        scatter_kernel<<<blocks, 256>>>(src, dst, e, n);
    }
    {   // K5: one warp per node
        int blocks = (n + 7) / 8;
        sddmm_csr_kernel<<<blocks, 256>>>(out, n);
    }
}